// round 3
// baseline (speedup 1.0000x reference)
#include <cuda_runtime.h>
#include <math.h>
#include <stdint.h>

// Problem constants
#define T_  64
#define B_  32
#define V_  8000
#define E_  256
#define H_  512
#define G_  2048          // 4*H
#define W_  3
#define N_  2048          // T*B
#define BB_ 64            // combined fwd+bwd encoder batch
#define NEGF (-1e30f)

// ---------------- static device scratch (no allocations allowed) ----------------
__device__ float g_enc_xw[(size_t)T_ * BB_ * G_];   // [t][bb][4H]
__device__ float g_hA[BB_ * H_];
__device__ float g_hB[BB_ * H_];
__device__ float g_cE[BB_ * H_];
__device__ float g_fwd_hid[(size_t)T_ * B_ * H_];   // [t][b][H]
__device__ float g_bwd_hid[(size_t)T_ * B_ * H_];
__device__ int   g_enc_tok[T_ * BB_];
__device__ int   g_dec_tok[(W_ + 1) * N_];
__device__ float g_dec_xw[(size_t)(W_ + 1) * N_ * G_]; // [s][r][4H]
__device__ float g_dec_g[(size_t)N_ * G_];
__device__ float g_dec_h[(size_t)N_ * H_];
__device__ float g_dec_c[(size_t)N_ * H_];
__device__ float g_logits[(size_t)N_ * V_];
__device__ float g_cum[N_];
__device__ float g_fres[W_ * N_];
__device__ float g_bres[W_ * N_];

__device__ __forceinline__ float sigf(float x) { return 1.0f / (1.0f + expf(-x)); }

// ---------------- token tables ----------------
__global__ void fill_enc_tok_k(const int* __restrict__ sent, int* __restrict__ tok) {
    int idx = blockIdx.x * blockDim.x + threadIdx.x;
    if (idx >= T_ * BB_) return;
    int t = idx / BB_, bb = idx % BB_;
    int v = 0;
    if (t > 0) {
        if (bb < B_) v = sent[bb * T_ + t - 1];             // fwd: toks[t]=sentence[t-1]
        else         v = sent[(bb - B_) * T_ + (T_ - t)];   // bwd: toks[t]=sentence[T-t]
    }
    tok[idx] = v;
}

__global__ void fill_dec_tok_k(const int* __restrict__ sent, int isBwd, int* __restrict__ tok) {
    int idx = blockIdx.x * blockDim.x + threadIdx.x;
    if (idx >= (W_ + 1) * N_) return;
    int s = idx / N_, r = idx % N_;
    int v = 0;
    if (s > 0) {
        int m = r / B_, b = r % B_;
        int pos = min(m + s - 1, T_ - 1);
        v = isBwd ? sent[b * T_ + (T_ - 1 - pos)] : sent[b * T_ + pos];
    }
    tok[idx] = v;
}

__global__ void zero2_k(float* __restrict__ a, float* __restrict__ b, int n) {
    int idx = blockIdx.x * blockDim.x + threadIdx.x;
    if (idx < n) { a[idx] = 0.f; b[idx] = 0.f; }
}

__global__ void dec_init_k(float* __restrict__ h, float* __restrict__ c, const float* __restrict__ hid) {
    int idx = blockIdx.x * blockDim.x + threadIdx.x;
    if (idx < N_ * H_) { float v = hid[idx]; h[idx] = v; c[idx] = v; }
}

// ---------------- generic NT GEMM: C[m][n] = dot(Arow(m), Brow(n)) + bias + addend ----------------
// A rows are optionally gathered through tok[] (embedding lookup fused in).
__global__ void __launch_bounds__(256) gemm_nt_k(
    const float* __restrict__ A, int lda, const int* __restrict__ tok,
    const float* __restrict__ Bm, int ldb,
    const float* __restrict__ bias, const float* __restrict__ addend, int ldadd,
    float* __restrict__ C, int ldc, int M, int N, int K)
{
    __shared__ __align__(16) float As[16][128];
    __shared__ __align__(16) float Bs[16][128];
    int tid = threadIdx.x;
    int m0 = blockIdx.y * 128, n0 = blockIdx.x * 128;
    int tx = tid & 15, ty = tid >> 4;
    int lr = tid >> 2, lc4 = tid & 3;

    const float* aptr[2]; const float* bptr[2];
    bool aval[2], bval[2];
#pragma unroll
    for (int hh = 0; hh < 2; hh++) {
        int m = m0 + lr + hh * 64;
        aval[hh] = (m < M);
        const float* p = A;
        if (aval[hh]) p = tok ? A + (size_t)tok[m] * lda : A + (size_t)m * lda;
        aptr[hh] = p;
        int n = n0 + lr + hh * 64;
        bval[hh] = (n < N);
        bptr[hh] = bval[hh] ? Bm + (size_t)n * ldb : Bm;
    }

    float acc[8][8];
#pragma unroll
    for (int i = 0; i < 8; i++)
#pragma unroll
        for (int j = 0; j < 8; j++) acc[i][j] = 0.f;

    for (int k0 = 0; k0 < K; k0 += 16) {
#pragma unroll
        for (int hh = 0; hh < 2; hh++) {
            float4 v = make_float4(0.f, 0.f, 0.f, 0.f);
            if (aval[hh]) v = *reinterpret_cast<const float4*>(aptr[hh] + k0 + lc4 * 4);
            As[lc4 * 4 + 0][lr + hh * 64] = v.x;
            As[lc4 * 4 + 1][lr + hh * 64] = v.y;
            As[lc4 * 4 + 2][lr + hh * 64] = v.z;
            As[lc4 * 4 + 3][lr + hh * 64] = v.w;
            float4 w = make_float4(0.f, 0.f, 0.f, 0.f);
            if (bval[hh]) w = *reinterpret_cast<const float4*>(bptr[hh] + k0 + lc4 * 4);
            Bs[lc4 * 4 + 0][lr + hh * 64] = w.x;
            Bs[lc4 * 4 + 1][lr + hh * 64] = w.y;
            Bs[lc4 * 4 + 2][lr + hh * 64] = w.z;
            Bs[lc4 * 4 + 3][lr + hh * 64] = w.w;
        }
        __syncthreads();
#pragma unroll
        for (int k = 0; k < 16; k++) {
            float4 a0 = *reinterpret_cast<const float4*>(&As[k][ty * 8]);
            float4 a1 = *reinterpret_cast<const float4*>(&As[k][ty * 8 + 4]);
            float4 b0 = *reinterpret_cast<const float4*>(&Bs[k][tx * 8]);
            float4 b1 = *reinterpret_cast<const float4*>(&Bs[k][tx * 8 + 4]);
            float ar[8] = {a0.x, a0.y, a0.z, a0.w, a1.x, a1.y, a1.z, a1.w};
            float br[8] = {b0.x, b0.y, b0.z, b0.w, b1.x, b1.y, b1.z, b1.w};
#pragma unroll
            for (int i = 0; i < 8; i++)
#pragma unroll
                for (int j = 0; j < 8; j++) acc[i][j] += ar[i] * br[j];
        }
        __syncthreads();
    }

#pragma unroll
    for (int i = 0; i < 8; i++) {
        int m = m0 + ty * 8 + i;
        if (m >= M) continue;
        float* crow = C + (size_t)m * ldc;
        const float* adr = addend ? addend + (size_t)m * ldadd : nullptr;
#pragma unroll
        for (int j = 0; j < 8; j++) {
            int n = n0 + tx * 8 + j;
            if (n >= N) continue;
            float v = acc[i][j];
            if (bias) v += bias[n];
            if (adr)  v += adr[n];
            crow[n] = v;
        }
    }
}

// ---------------- fused encoder LSTM step (M=64 recurrence) ----------------
// grid = 128 blocks (4 h-cols each), 256 threads = 8 warps.
// warp -> (col = blk*4 + warp/2, row half); lane -> row. No cross-lane reductions.
__global__ void __launch_bounds__(256) enc_step_k(
    const float* __restrict__ xw, const float* __restrict__ Whh,
    const float* __restrict__ hprev, float* __restrict__ cst,
    float* __restrict__ hnext, float* __restrict__ fhid, float* __restrict__ bhid, int t)
{
    __shared__ float hs[BB_][33];
    int tid = threadIdx.x, warp = tid >> 5, lane = tid & 31;
    int c = blockIdx.x * 4 + (warp >> 1);
    int row = ((warp & 1) << 5) + lane;
    const float* wi = Whh + (size_t)(0 * H_ + c) * H_;
    const float* wf = Whh + (size_t)(1 * H_ + c) * H_;
    const float* wg = Whh + (size_t)(2 * H_ + c) * H_;
    const float* wo = Whh + (size_t)(3 * H_ + c) * H_;
    float ai = 0.f, af = 0.f, ag = 0.f, ao = 0.f;
    for (int k0 = 0; k0 < H_; k0 += 32) {
        __syncthreads();
        for (int li = tid; li < BB_ * 8; li += 256) {
            int r = li >> 3, c4 = li & 7;
            float4 v = *reinterpret_cast<const float4*>(hprev + (size_t)r * H_ + k0 + c4 * 4);
            hs[r][c4 * 4 + 0] = v.x; hs[r][c4 * 4 + 1] = v.y;
            hs[r][c4 * 4 + 2] = v.z; hs[r][c4 * 4 + 3] = v.w;
        }
        __syncthreads();
#pragma unroll
        for (int kk = 0; kk < 32; kk++) {
            float hv = hs[row][kk];
            ai += wi[k0 + kk] * hv;
            af += wf[k0 + kk] * hv;
            ag += wg[k0 + kk] * hv;
            ao += wo[k0 + kk] * hv;
        }
    }
    size_t xb = (size_t)row * G_;
    float gi = ai + xw[xb + c];
    float gf = af + xw[xb + H_ + c];
    float gg = ag + xw[xb + 2 * H_ + c];
    float go = ao + xw[xb + 3 * H_ + c];
    float I = sigf(gi), F = sigf(gf), Gv = tanhf(gg), O = sigf(go);
    size_t hi = (size_t)row * H_ + c;
    float cn = F * cst[hi] + I * Gv;
    cst[hi] = cn;
    float hn = O * tanhf(cn);
    hnext[hi] = hn;
    if (row < B_) fhid[((size_t)t * B_ + row) * H_ + c] = hn;
    else          bhid[((size_t)t * B_ + (row - B_)) * H_ + c] = hn;
}

// ---------------- decoder pointwise gates ----------------
__global__ void dec_gates_k(float* __restrict__ h, float* __restrict__ c, const float* __restrict__ g) {
    int idx = blockIdx.x * blockDim.x + threadIdx.x;
    if (idx >= N_ * H_) return;
    int r = idx >> 9, col = idx & 511;
    const float* gr = g + (size_t)r * G_;
    float I = sigf(gr[col]);
    float F = sigf(gr[H_ + col]);
    float Gv = tanhf(gr[2 * H_ + col]);
    float O = sigf(gr[3 * H_ + col]);
    float cn = F * c[idx] + I * Gv;
    c[idx] = cn;
    h[idx] = O * tanhf(cn);
}

// ---------------- per-row logsumexp over V + segment log-prob bookkeeping ----------------
__global__ void __launch_bounds__(256) reduce_k(
    const float* __restrict__ logits, const int* __restrict__ sent,
    float* __restrict__ cum, float* __restrict__ res, int s, int isBwd)
{
    __shared__ float sr[256];
    int r = blockIdx.x, tid = threadIdx.x;
    const float* row = logits + (size_t)r * V_;
    float lm = -3.402823e38f;
    for (int i = tid; i < V_; i += 256) lm = fmaxf(lm, row[i]);
    sr[tid] = lm; __syncthreads();
    for (int o = 128; o > 0; o >>= 1) { if (tid < o) sr[tid] = fmaxf(sr[tid], sr[tid + o]); __syncthreads(); }
    float mx = sr[0]; __syncthreads();
    float lsum = 0.f;
    for (int i = tid; i < V_; i += 256) lsum += expf(row[i] - mx);
    sr[tid] = lsum; __syncthreads();
    for (int o = 128; o > 0; o >>= 1) { if (tid < o) sr[tid] += sr[tid + o]; __syncthreads(); }
    if (tid == 0) {
        float logZ = mx + logf(sr[0]);
        int m = r / B_, b = r % B_;
        if (s < W_) {
            int pos = min(m + s, T_ - 1);
            int y = isBwd ? sent[b * T_ + (T_ - 1 - pos)] : sent[b * T_ + pos];
            float lpy = row[y] - logZ;
            if (s == 0) {
                cum[r] = lpy;
            } else {
                float tag = row[0] - logZ;
                res[(s - 1) * N_ + r] = cum[r] + tag;
                cum[r] += lpy;
            }
        } else {
            float tag = row[0] - logZ;
            res[(W_ - 1) * N_ + r] = cum[r] + tag;
        }
    }
}

// ---------------- add_bidirection + semi-Markov DP + mean ----------------
__global__ void final_k(const float* __restrict__ fres, const float* __restrict__ bres, float* __restrict__ out) {
    int b = threadIdx.x; // 32 threads, one per batch element
    float b0 = 0.f, b1 = NEGF, b2 = NEGF;
    for (int e = 0; e < T_; e++) {
        int br = (T_ - 1 - e) * B_ + b;
        float p0 = fres[0 * N_ + e * B_ + b] + bres[0 * N_ + br];
        float p1 = (e >= 1) ? fres[1 * N_ + (e - 1) * B_ + b] + bres[1 * N_ + br] : NEGF;
        float p2 = (e >= 2) ? fres[2 * N_ + (e - 2) * B_ + b] + bres[2 * N_ + br] : NEGF;
        float v0 = b0 + p0, v1 = b1 + p1, v2 = b2 + p2;
        float mx = fmaxf(v0, fmaxf(v1, v2));
        float tot = mx + logf(expf(v0 - mx) + expf(v1 - mx) + expf(v2 - mx));
        b2 = b1; b1 = b0; b0 = tot;
    }
    float sum = b0;
    for (int o = 16; o > 0; o >>= 1) sum += __shfl_xor_sync(0xffffffffu, sum, o);
    if (b == 0) out[0] = -sum / (float)B_;
}

// ---------------- host launcher ----------------
extern "C" void kernel_launch(void* const* d_in, const int* in_sizes, int n_in,
                              void* d_out, int out_size)
{
    const int*   sent = (const int*)d_in[0];
    const float* emb  = (const float*)d_in[1];
    const float* eWih = (const float*)d_in[2];
    const float* eWhh = (const float*)d_in[3];
    const float* eb   = (const float*)d_in[4];
    const float* dWih[2] = {(const float*)d_in[5],  (const float*)d_in[10]};
    const float* dWhh[2] = {(const float*)d_in[6],  (const float*)d_in[11]};
    const float* db[2]   = {(const float*)d_in[7],  (const float*)d_in[12]};
    const float* dhW[2]  = {(const float*)d_in[8],  (const float*)d_in[13]};
    const float* dhb[2]  = {(const float*)d_in[9],  (const float*)d_in[14]};

    float *enc_xw, *hA, *hB, *cE, *fhid, *bhid, *dxw, *dg, *dh, *dc, *lgt, *cum, *fres, *bres;
    int *etok, *dtok;
    cudaGetSymbolAddress((void**)&enc_xw, g_enc_xw);
    cudaGetSymbolAddress((void**)&hA, g_hA);
    cudaGetSymbolAddress((void**)&hB, g_hB);
    cudaGetSymbolAddress((void**)&cE, g_cE);
    cudaGetSymbolAddress((void**)&fhid, g_fwd_hid);
    cudaGetSymbolAddress((void**)&bhid, g_bwd_hid);
    cudaGetSymbolAddress((void**)&dxw, g_dec_xw);
    cudaGetSymbolAddress((void**)&dg, g_dec_g);
    cudaGetSymbolAddress((void**)&dh, g_dec_h);
    cudaGetSymbolAddress((void**)&dc, g_dec_c);
    cudaGetSymbolAddress((void**)&lgt, g_logits);
    cudaGetSymbolAddress((void**)&cum, g_cum);
    cudaGetSymbolAddress((void**)&fres, g_fres);
    cudaGetSymbolAddress((void**)&bres, g_bres);
    cudaGetSymbolAddress((void**)&etok, g_enc_tok);
    cudaGetSymbolAddress((void**)&dtok, g_dec_tok);

    // Encoder (fwd+bwd combined, batch 64)
    fill_enc_tok_k<<<(T_ * BB_ + 255) / 256, 256>>>(sent, etok);
    zero2_k<<<(BB_ * H_ + 255) / 256, 256>>>(hA, cE, BB_ * H_);
    {
        dim3 grid(G_ / 128, (T_ * BB_) / 128);
        gemm_nt_k<<<grid, 256>>>(emb, E_, etok, eWih, E_, eb, nullptr, 0,
                                 enc_xw, G_, T_ * BB_, G_, E_);
    }
    for (int t = 0; t < T_; t++) {
        const float* hp = (t & 1) ? hB : hA;
        float* hn = (t & 1) ? hA : hB;
        enc_step_k<<<H_ / 4, 256>>>(enc_xw + (size_t)t * BB_ * G_, eWhh, hp, cE, hn, fhid, bhid, t);
    }

    // Decoders (fwd then bwd)
    for (int d = 0; d < 2; d++) {
        float* hid = d ? bhid : fhid;
        float* res = d ? bres : fres;
        fill_dec_tok_k<<<((W_ + 1) * N_ + 255) / 256, 256>>>(sent, d, dtok);
        {
            dim3 grid(G_ / 128, ((W_ + 1) * N_) / 128);
            gemm_nt_k<<<grid, 256>>>(emb, E_, dtok, dWih[d], E_, db[d], nullptr, 0,
                                     dxw, G_, (W_ + 1) * N_, G_, E_);
        }
        dec_init_k<<<(N_ * H_ + 255) / 256, 256>>>(dh, dc, hid);
        for (int s = 0; s <= W_; s++) {
            dim3 gridg(G_ / 128, N_ / 128);
            gemm_nt_k<<<gridg, 256>>>(dh, H_, nullptr, dWhh[d], H_, nullptr,
                                      dxw + (size_t)s * N_ * G_, G_, dg, G_, N_, G_, H_);
            dec_gates_k<<<(N_ * H_ + 255) / 256, 256>>>(dh, dc, dg);
            dim3 gridl((V_ + 127) / 128, N_ / 128);
            gemm_nt_k<<<gridl, 256>>>(dh, H_, nullptr, dhW[d], H_, dhb[d], nullptr, 0,
                                      lgt, V_, N_, V_, H_);
            reduce_k<<<N_, 256>>>(lgt, sent, cum, res, s, d);
        }
    }

    final_k<<<1, 32>>>(fres, bres, (float*)d_out);
}

// round 11
// speedup vs baseline: 1.9416x; 1.9416x over previous
#include <cuda_runtime.h>
#include <math.h>
#include <stdint.h>

// Problem constants
#define T_  64
#define B_  32
#define V_  8000
#define E_  256
#define H_  512
#define G_  2048          // 4*H
#define W_  3
#define N_  2048          // T*B
#define BB_ 64            // combined fwd+bwd encoder batch
#define NEGF (-1e30f)
#define ENC_BLOCKS 128

// ---------------- static device scratch (no allocations allowed) ----------------
__device__ float g_enc_xw[(size_t)T_ * BB_ * G_];   // [t][bb][4H]
__device__ float g_hbuf[3 * BB_ * H_];              // triple-buffered h state
__device__ unsigned g_bar;                          // grid barrier counter
__device__ float g_fwd_hid[(size_t)T_ * B_ * H_];   // [t][b][H]
__device__ float g_bwd_hid[(size_t)T_ * B_ * H_];
__device__ int   g_enc_tok[T_ * BB_];
__device__ int   g_dec_tok[(W_ + 1) * N_];
__device__ float g_dec_xw[(size_t)(W_ + 1) * N_ * G_]; // [s][r][4H]
__device__ float g_dec_g[(size_t)N_ * G_];
__device__ float g_dec_h[(size_t)N_ * H_];
__device__ float g_dec_c[(size_t)N_ * H_];
__device__ float g_logits[(size_t)N_ * V_];
__device__ float g_cum[N_];
__device__ float g_fres[W_ * N_];
__device__ float g_bres[W_ * N_];

__device__ __forceinline__ float sigf(float x) { return 1.0f / (1.0f + expf(-x)); }

__device__ __forceinline__ uint32_t f2tf32(float f) {
    uint32_t u;
    asm("cvt.rna.tf32.f32 %0, %1;" : "=r"(u) : "f"(f));
    return u;
}

// ---------------- token tables ----------------
__global__ void fill_enc_tok_k(const int* __restrict__ sent, int* __restrict__ tok) {
    int idx = blockIdx.x * blockDim.x + threadIdx.x;
    if (idx >= T_ * BB_) return;
    int t = idx / BB_, bb = idx % BB_;
    int v = 0;
    if (t > 0) {
        if (bb < B_) v = sent[bb * T_ + t - 1];             // fwd: toks[t]=sentence[t-1]
        else         v = sent[(bb - B_) * T_ + (T_ - t)];   // bwd: toks[t]=sentence[T-t]
    }
    tok[idx] = v;
}

__global__ void fill_dec_tok_k(const int* __restrict__ sent, int isBwd, int* __restrict__ tok) {
    int idx = blockIdx.x * blockDim.x + threadIdx.x;
    if (idx >= (W_ + 1) * N_) return;
    int s = idx / N_, r = idx % N_;
    int v = 0;
    if (s > 0) {
        int m = r / B_, b = r % B_;
        int pos = min(m + s - 1, T_ - 1);
        v = isBwd ? sent[b * T_ + (T_ - 1 - pos)] : sent[b * T_ + pos];
    }
    tok[idx] = v;
}

// zero h buffer 0 + barrier counter (must run every launch/replay)
__global__ void enc_init_k(float* __restrict__ hbuf0, unsigned* __restrict__ bar) {
    int idx = blockIdx.x * blockDim.x + threadIdx.x;
    if (idx == 0) *bar = 0u;
    if (idx < BB_ * H_) hbuf0[idx] = 0.f;
}

__global__ void dec_init_k(float* __restrict__ h, float* __restrict__ c, const float* __restrict__ hid) {
    int idx = blockIdx.x * blockDim.x + threadIdx.x;
    if (idx < N_ * H_) { float v = hid[idx]; h[idx] = v; c[idx] = v; }
}

// ---------------- tf32 tensor-core NT GEMM ----------------
// C[m][n] = dot(Arow(m), Brow(n)) + bias[n] + addend[m][n]
// A rows optionally gathered through tok[]. Block tile 128x128, k-chunk 32.
// 8 warps as 2(M)x4(N); warp tile 64x32 = 4x4 m16n8k8 mma tiles.
// Requires: M % 128 == 0, K % 32 == 0 (true for all call sites); N guarded.
__global__ void __launch_bounds__(256) gemm_tf32_k(
    const float* __restrict__ A, int lda, const int* __restrict__ tok,
    const float* __restrict__ Bm, int ldb,
    const float* __restrict__ bias, const float* __restrict__ addend, int ldadd,
    float* __restrict__ C, int ldc, int M, int N, int K)
{
    __shared__ uint32_t As[128][36];   // padded: frag loads conflict-free
    __shared__ uint32_t Bs[128][36];
    int tid = threadIdx.x;
    int warp = tid >> 5, lane = tid & 31;
    int wm = warp >> 2, wn = warp & 3;      // 2 x 4 warp grid
    int g = lane >> 2, cq = lane & 3;       // groupID, threadID-in-group
    int m0 = blockIdx.y * 128, n0 = blockIdx.x * 128;

    float acc[4][4][4];
#pragma unroll
    for (int i = 0; i < 4; i++)
#pragma unroll
        for (int j = 0; j < 4; j++)
#pragma unroll
            for (int r = 0; r < 4; r++) acc[i][j][r] = 0.f;

    for (int k0 = 0; k0 < K; k0 += 32) {
        __syncthreads();
        for (int i = tid; i < 1024; i += 256) {
            int r = i >> 3, c4 = i & 7;
            {
                int m = m0 + r;
                const float* arow = tok ? A + (size_t)tok[m] * lda : A + (size_t)m * lda;
                float4 v = *reinterpret_cast<const float4*>(arow + k0 + c4 * 4);
                uint4 u = make_uint4(f2tf32(v.x), f2tf32(v.y), f2tf32(v.z), f2tf32(v.w));
                *reinterpret_cast<uint4*>(&As[r][c4 * 4]) = u;
            }
            {
                int n = n0 + r;
                const float* brow = (n < N) ? Bm + (size_t)n * ldb : Bm;
                float4 v = *reinterpret_cast<const float4*>(brow + k0 + c4 * 4);
                uint4 u = make_uint4(f2tf32(v.x), f2tf32(v.y), f2tf32(v.z), f2tf32(v.w));
                *reinterpret_cast<uint4*>(&Bs[r][c4 * 4]) = u;
            }
        }
        __syncthreads();
#pragma unroll
        for (int kk = 0; kk < 32; kk += 8) {
            uint32_t af[4][4], bf[4][2];
#pragma unroll
            for (int tm = 0; tm < 4; tm++) {
                int rb = wm * 64 + tm * 16;
                af[tm][0] = As[rb + g][kk + cq];
                af[tm][1] = As[rb + g + 8][kk + cq];
                af[tm][2] = As[rb + g][kk + cq + 4];
                af[tm][3] = As[rb + g + 8][kk + cq + 4];
            }
#pragma unroll
            for (int tn = 0; tn < 4; tn++) {
                int cb = wn * 32 + tn * 8;
                bf[tn][0] = Bs[cb + g][kk + cq];
                bf[tn][1] = Bs[cb + g][kk + cq + 4];
            }
#pragma unroll
            for (int tm = 0; tm < 4; tm++)
#pragma unroll
                for (int tn = 0; tn < 4; tn++) {
                    asm volatile(
                        "mma.sync.aligned.m16n8k8.row.col.f32.tf32.tf32.f32 "
                        "{%0,%1,%2,%3}, {%4,%5,%6,%7}, {%8,%9}, {%0,%1,%2,%3};"
                        : "+f"(acc[tm][tn][0]), "+f"(acc[tm][tn][1]),
                          "+f"(acc[tm][tn][2]), "+f"(acc[tm][tn][3])
                        : "r"(af[tm][0]), "r"(af[tm][1]), "r"(af[tm][2]), "r"(af[tm][3]),
                          "r"(bf[tn][0]), "r"(bf[tn][1]));
                }
        }
    }

    // epilogue: c0:(g,2cq) c1:(g,2cq+1) c2:(g+8,2cq) c3:(g+8,2cq+1)
#pragma unroll
    for (int tm = 0; tm < 4; tm++) {
        int rowA = m0 + wm * 64 + tm * 16 + g;
        int rowB = rowA + 8;
        const float* adA = addend ? addend + (size_t)rowA * ldadd : nullptr;
        const float* adB = addend ? addend + (size_t)rowB * ldadd : nullptr;
        float* cA = C + (size_t)rowA * ldc;
        float* cB = C + (size_t)rowB * ldc;
#pragma unroll
        for (int tn = 0; tn < 4; tn++) {
            int col = n0 + wn * 32 + tn * 8 + cq * 2;
            if (col < N) {   // N is even at all call sites, so col+1 < N too
                float b0 = bias ? bias[col] : 0.f;
                float b1 = bias ? bias[col + 1] : 0.f;
                cA[col]     = acc[tm][tn][0] + b0 + (adA ? adA[col] : 0.f);
                cA[col + 1] = acc[tm][tn][1] + b1 + (adA ? adA[col + 1] : 0.f);
                cB[col]     = acc[tm][tn][2] + b0 + (adB ? adB[col] : 0.f);
                cB[col + 1] = acc[tm][tn][3] + b1 + (adB ? adB[col + 1] : 0.f);
            }
        }
    }
}

// ---------------- persistent encoder LSTM (all 64 steps, one launch) ----------------
// 128 blocks x 256 threads, all co-resident (<= 148 SMs). Block b owns h-columns
// 4b..4b+3; Whh slice in smem as float4 (wi,wf,wg,wo) per k. Cell state in a
// register. h flows through a TRIPLE-buffered global array with one counter
// grid-barrier per step (counter zeroed each replay by enc_init_k).
__global__ void __launch_bounds__(256) enc_persist_k(
    const float* __restrict__ xw, const float* __restrict__ Whh,
    float* __restrict__ hbuf,
    float* __restrict__ fhid, float* __restrict__ bhid,
    unsigned* __restrict__ bar)
{
    __shared__ __align__(16) float4 wsm[4][H_];   // 32 KB
    __shared__ float hs[BB_][33];                 // 8.25 KB staging

    int tid = threadIdx.x, warp = tid >> 5, lane = tid & 31;
    int cl = warp >> 1;                  // local column 0..3
    int c = blockIdx.x * 4 + cl;         // global h column
    int row = ((warp & 1) << 5) + lane;  // batch row 0..63

    for (int i = tid; i < 4 * H_; i += 256) {
        int icl = i >> 9, k = i & (H_ - 1);
        int cc = blockIdx.x * 4 + icl;
        wsm[icl][k] = make_float4(
            Whh[(size_t)(0 * H_ + cc) * H_ + k],
            Whh[(size_t)(1 * H_ + cc) * H_ + k],
            Whh[(size_t)(2 * H_ + cc) * H_ + k],
            Whh[(size_t)(3 * H_ + cc) * H_ + k]);
    }

    float cstate = 0.f;
    unsigned nb = gridDim.x;

    for (int t = 0; t < T_; t++) {
        const float* hprev = hbuf + (size_t)(t % 3) * (BB_ * H_);
        float* hnext = hbuf + (size_t)((t + 1) % 3) * (BB_ * H_);

        float ai = 0.f, af = 0.f, ag = 0.f, ao = 0.f;
        for (int k0 = 0; k0 < H_; k0 += 32) {
            __syncthreads();
            for (int li = tid; li < BB_ * 8; li += 256) {
                int r = li >> 3, c4 = li & 7;
                float4 v = __ldcg(reinterpret_cast<const float4*>(hprev + (size_t)r * H_ + k0) + c4);
                hs[r][c4 * 4 + 0] = v.x; hs[r][c4 * 4 + 1] = v.y;
                hs[r][c4 * 4 + 2] = v.z; hs[r][c4 * 4 + 3] = v.w;
            }
            __syncthreads();
#pragma unroll
            for (int kk = 0; kk < 32; kk++) {
                float hv = hs[row][kk];
                float4 w = wsm[cl][k0 + kk];
                ai += w.x * hv; af += w.y * hv; ag += w.z * hv; ao += w.w * hv;
            }
        }

        const float* xrow = xw + ((size_t)t * BB_ + row) * G_;
        float gi = ai + xrow[c];
        float gf = af + xrow[H_ + c];
        float gg = ag + xrow[2 * H_ + c];
        float go = ao + xrow[3 * H_ + c];
        float I = sigf(gi), F = sigf(gf), Gv = tanhf(gg), O = sigf(go);
        cstate = F * cstate + I * Gv;
        float hn = O * tanhf(cstate);
        hnext[(size_t)row * H_ + c] = hn;
        if (row < B_) fhid[((size_t)t * B_ + row) * H_ + c] = hn;
        else          bhid[((size_t)t * B_ + (row - B_)) * H_ + c] = hn;

        if (t == T_ - 1) break;

        __threadfence();
        __syncthreads();
        if (tid == 0) {
            atomicAdd(bar, 1u);
            unsigned target = (unsigned)(t + 1) * nb;
            while (atomicAdd(bar, 0u) < target) __nanosleep(40);
        }
        __syncthreads();
    }
}

// ---------------- decoder pointwise gates ----------------
__global__ void dec_gates_k(float* __restrict__ h, float* __restrict__ c, const float* __restrict__ g) {
    int idx = blockIdx.x * blockDim.x + threadIdx.x;
    if (idx >= N_ * H_) return;
    int r = idx >> 9, col = idx & 511;
    const float* gr = g + (size_t)r * G_;
    float I = sigf(gr[col]);
    float F = sigf(gr[H_ + col]);
    float Gv = tanhf(gr[2 * H_ + col]);
    float O = sigf(gr[3 * H_ + col]);
    float cn = F * c[idx] + I * Gv;
    c[idx] = cn;
    h[idx] = O * tanhf(cn);
}

// ---------------- per-row ONLINE logsumexp over V (single pass) + bookkeeping ----------------
__global__ void __launch_bounds__(256) reduce_k(
    const float* __restrict__ logits, const int* __restrict__ sent,
    float* __restrict__ cum, float* __restrict__ res, int s, int isBwd)
{
    __shared__ float sm[256];
    __shared__ float ss[256];
    int r = blockIdx.x, tid = threadIdx.x;
    const float* row = logits + (size_t)r * V_;
    float m = NEGF, su = 0.f;
    for (int i = tid; i < V_; i += 256) {
        float v = row[i];
        if (v > m) { su = su * expf(m - v) + 1.0f; m = v; }
        else       { su += expf(v - m); }
    }
    sm[tid] = m; ss[tid] = su; __syncthreads();
    for (int o = 128; o > 0; o >>= 1) {
        if (tid < o) {
            float ma = sm[tid], mb = sm[tid + o];
            float sa = ss[tid], sb = ss[tid + o];
            float mm = fmaxf(ma, mb);
            sm[tid] = mm;
            ss[tid] = sa * expf(ma - mm) + sb * expf(mb - mm);
        }
        __syncthreads();
    }
    if (tid == 0) {
        float logZ = sm[0] + logf(ss[0]);
        int mrow = r / B_, b = r % B_;
        if (s < W_) {
            int pos = min(mrow + s, T_ - 1);
            int y = isBwd ? sent[b * T_ + (T_ - 1 - pos)] : sent[b * T_ + pos];
            float lpy = row[y] - logZ;
            if (s == 0) {
                cum[r] = lpy;
            } else {
                float tag = row[0] - logZ;
                res[(s - 1) * N_ + r] = cum[r] + tag;
                cum[r] += lpy;
            }
        } else {
            float tag = row[0] - logZ;
            res[(W_ - 1) * N_ + r] = cum[r] + tag;
        }
    }
}

// ---------------- add_bidirection + semi-Markov DP + mean ----------------
__global__ void final_k(const float* __restrict__ fres, const float* __restrict__ bres, float* __restrict__ out) {
    int b = threadIdx.x;
    float b0 = 0.f, b1 = NEGF, b2 = NEGF;
    for (int e = 0; e < T_; e++) {
        int br = (T_ - 1 - e) * B_ + b;
        float p0 = fres[0 * N_ + e * B_ + b] + bres[0 * N_ + br];
        float p1 = (e >= 1) ? fres[1 * N_ + (e - 1) * B_ + b] + bres[1 * N_ + br] : NEGF;
        float p2 = (e >= 2) ? fres[2 * N_ + (e - 2) * B_ + b] + bres[2 * N_ + br] : NEGF;
        float v0 = b0 + p0, v1 = b1 + p1, v2 = b2 + p2;
        float mx = fmaxf(v0, fmaxf(v1, v2));
        float tot = mx + logf(expf(v0 - mx) + expf(v1 - mx) + expf(v2 - mx));
        b2 = b1; b1 = b0; b0 = tot;
    }
    float sum = b0;
    for (int o = 16; o > 0; o >>= 1) sum += __shfl_xor_sync(0xffffffffu, sum, o);
    if (b == 0) out[0] = -sum / (float)B_;
}

// ---------------- host launcher ----------------
extern "C" void kernel_launch(void* const* d_in, const int* in_sizes, int n_in,
                              void* d_out, int out_size)
{
    const int*   sent = (const int*)d_in[0];
    const float* emb  = (const float*)d_in[1];
    const float* eWih = (const float*)d_in[2];
    const float* eWhh = (const float*)d_in[3];
    const float* eb   = (const float*)d_in[4];
    const float* dWih[2] = {(const float*)d_in[5],  (const float*)d_in[10]};
    const float* dWhh[2] = {(const float*)d_in[6],  (const float*)d_in[11]};
    const float* db[2]   = {(const float*)d_in[7],  (const float*)d_in[12]};
    const float* dhW[2]  = {(const float*)d_in[8],  (const float*)d_in[13]};
    const float* dhb[2]  = {(const float*)d_in[9],  (const float*)d_in[14]};

    float *enc_xw, *hbuf, *fhid, *bhid, *dxw, *dg, *dh, *dc, *lgt, *cum, *fres, *bres;
    int *etok, *dtok;
    unsigned *bar;
    cudaGetSymbolAddress((void**)&enc_xw, g_enc_xw);
    cudaGetSymbolAddress((void**)&hbuf, g_hbuf);
    cudaGetSymbolAddress((void**)&bar, g_bar);
    cudaGetSymbolAddress((void**)&fhid, g_fwd_hid);
    cudaGetSymbolAddress((void**)&bhid, g_bwd_hid);
    cudaGetSymbolAddress((void**)&dxw, g_dec_xw);
    cudaGetSymbolAddress((void**)&dg, g_dec_g);
    cudaGetSymbolAddress((void**)&dh, g_dec_h);
    cudaGetSymbolAddress((void**)&dc, g_dec_c);
    cudaGetSymbolAddress((void**)&lgt, g_logits);
    cudaGetSymbolAddress((void**)&cum, g_cum);
    cudaGetSymbolAddress((void**)&fres, g_fres);
    cudaGetSymbolAddress((void**)&bres, g_bres);
    cudaGetSymbolAddress((void**)&etok, g_enc_tok);
    cudaGetSymbolAddress((void**)&dtok, g_dec_tok);

    // Encoder (fwd+bwd combined, batch 64)
    fill_enc_tok_k<<<(T_ * BB_ + 255) / 256, 256>>>(sent, etok);
    enc_init_k<<<(BB_ * H_ + 255) / 256, 256>>>(hbuf, bar);
    {
        dim3 grid(G_ / 128, (T_ * BB_) / 128);
        gemm_tf32_k<<<grid, 256>>>(emb, E_, etok, eWih, E_, eb, nullptr, 0,
                                   enc_xw, G_, T_ * BB_, G_, E_);
    }
    enc_persist_k<<<ENC_BLOCKS, 256>>>(enc_xw, eWhh, hbuf, fhid, bhid, bar);

    // Decoders (fwd then bwd)
    for (int d = 0; d < 2; d++) {
        float* hid = d ? bhid : fhid;
        float* res = d ? bres : fres;
        fill_dec_tok_k<<<((W_ + 1) * N_ + 255) / 256, 256>>>(sent, d, dtok);
        {
            dim3 grid(G_ / 128, ((W_ + 1) * N_) / 128);
            gemm_tf32_k<<<grid, 256>>>(emb, E_, dtok, dWih[d], E_, db[d], nullptr, 0,
                                       dxw, G_, (W_ + 1) * N_, G_, E_);
        }
        dec_init_k<<<(N_ * H_ + 255) / 256, 256>>>(dh, dc, hid);
        for (int s = 0; s <= W_; s++) {
            dim3 gridg(G_ / 128, N_ / 128);
            gemm_tf32_k<<<gridg, 256>>>(dh, H_, nullptr, dWhh[d], H_, nullptr,
                                        dxw + (size_t)s * N_ * G_, G_, dg, G_, N_, G_, H_);
            dec_gates_k<<<(N_ * H_ + 255) / 256, 256>>>(dh, dc, dg);
            dim3 gridl((V_ + 127) / 128, N_ / 128);
            gemm_tf32_k<<<gridl, 256>>>(dh, H_, nullptr, dhW[d], H_, dhb[d], nullptr, 0,
                                        lgt, V_, N_, V_, H_);
            reduce_k<<<N_, 256>>>(lgt, sent, cum, res, s, d);
        }
    }

    final_k<<<1, 32>>>(fres, bres, (float*)d_out);
}

// round 12
// speedup vs baseline: 2.2621x; 1.1651x over previous
#include <cuda_runtime.h>
#include <math.h>
#include <stdint.h>

// Problem constants
#define T_  64
#define B_  32
#define V_  8000
#define E_  256
#define H_  512
#define G_  2048          // 4*H
#define W_  3
#define N_  2048          // T*B
#define BB_ 64            // combined fwd+bwd encoder batch
#define NEGF (-1e30f)
#define ENC_BLOCKS 128

#define GSTAGES 3
#define GROW    36        // padded row (uint32) for conflict-free frag loads
#define GSMEM_BYTES (GSTAGES * 2 * 128 * GROW * 4)   // 110,592 B

// ---------------- static device scratch (no allocations allowed) ----------------
__device__ float g_enc_xw[(size_t)T_ * BB_ * G_];   // [t][bb][4H]
__device__ float g_hbuf[3 * BB_ * H_];              // triple-buffered h state
__device__ unsigned g_bar;                          // grid barrier counter
__device__ float g_fwd_hid[(size_t)T_ * B_ * H_];   // [t][b][H]
__device__ float g_bwd_hid[(size_t)T_ * B_ * H_];
__device__ int   g_enc_tok[T_ * BB_];
__device__ int   g_dec_tok[(W_ + 1) * N_];
__device__ float g_dec_xw[(size_t)(W_ + 1) * N_ * G_]; // [s][r][4H]
__device__ float g_dec_g[(size_t)N_ * G_];
__device__ float g_dec_h[(size_t)N_ * H_];
__device__ float g_dec_c[(size_t)N_ * H_];
__device__ float g_logits[(size_t)N_ * V_];
__device__ float g_cum[N_];
__device__ float g_fres[W_ * N_];
__device__ float g_bres[W_ * N_];

__device__ __forceinline__ float sigf(float x) { return 1.0f / (1.0f + expf(-x)); }

__device__ __forceinline__ void cp16(void* dst_smem, const void* src_gmem) {
    uint32_t d = (uint32_t)__cvta_generic_to_shared(dst_smem);
    asm volatile("cp.async.cg.shared.global [%0], [%1], 16;" :: "r"(d), "l"(src_gmem));
}
__device__ __forceinline__ void cp_commit() { asm volatile("cp.async.commit_group;"); }
__device__ __forceinline__ void cp_wait1()  { asm volatile("cp.async.wait_group 1;"); }

// ---------------- token tables ----------------
__global__ void fill_enc_tok_k(const int* __restrict__ sent, int* __restrict__ tok) {
    int idx = blockIdx.x * blockDim.x + threadIdx.x;
    if (idx >= T_ * BB_) return;
    int t = idx / BB_, bb = idx % BB_;
    int v = 0;
    if (t > 0) {
        if (bb < B_) v = sent[bb * T_ + t - 1];             // fwd: toks[t]=sentence[t-1]
        else         v = sent[(bb - B_) * T_ + (T_ - t)];   // bwd: toks[t]=sentence[T-t]
    }
    tok[idx] = v;
}

__global__ void fill_dec_tok_k(const int* __restrict__ sent, int isBwd, int* __restrict__ tok) {
    int idx = blockIdx.x * blockDim.x + threadIdx.x;
    if (idx >= (W_ + 1) * N_) return;
    int s = idx / N_, r = idx % N_;
    int v = 0;
    if (s > 0) {
        int m = r / B_, b = r % B_;
        int pos = min(m + s - 1, T_ - 1);
        v = isBwd ? sent[b * T_ + (T_ - 1 - pos)] : sent[b * T_ + pos];
    }
    tok[idx] = v;
}

// zero h buffer 0 + barrier counter (must run every launch/replay)
__global__ void enc_init_k(float* __restrict__ hbuf0, unsigned* __restrict__ bar) {
    int idx = blockIdx.x * blockDim.x + threadIdx.x;
    if (idx == 0) *bar = 0u;
    if (idx < BB_ * H_) hbuf0[idx] = 0.f;
}

__global__ void dec_init_k(float* __restrict__ h, float* __restrict__ c, const float* __restrict__ hid) {
    int idx = blockIdx.x * blockDim.x + threadIdx.x;
    if (idx < N_ * H_) { float v = hid[idx]; h[idx] = v; c[idx] = v; }
}

// ---------------- tf32 tensor-core NT GEMM, 3-stage cp.async pipeline ----------------
// C[m][n] = dot(Arow(m), Brow(n)) + bias[n] + addend[m][n]
// A rows optionally gathered through tok[]. Block tile 128x128, k-chunk 32.
// 8 warps as 2(M)x4(N); warp tile 64x32 = 4x4 m16n8k8 mma tiles.
// fp32 bits fed to HMMA.tf32 directly (HW reads upper 19 bits = truncation).
// Requires: M % 128 == 0, K % 64 == 0 (>= 2 chunks); N guarded (even).
__global__ void __launch_bounds__(256) gemm_tf32_k(
    const float* __restrict__ A, int lda, const int* __restrict__ tok,
    const float* __restrict__ Bm, int ldb,
    const float* __restrict__ bias, const float* __restrict__ addend, int ldadd,
    float* __restrict__ C, int ldc, int M, int N, int K)
{
    extern __shared__ uint32_t smem[];
    typedef uint32_t tile_t[128][GROW];
    tile_t* As = reinterpret_cast<tile_t*>(smem);                          // [GSTAGES]
    tile_t* Bs = reinterpret_cast<tile_t*>(smem + GSTAGES * 128 * GROW);   // [GSTAGES]

    int tid = threadIdx.x;
    int warp = tid >> 5, lane = tid & 31;
    int wm = warp >> 2, wn = warp & 3;      // 2 x 4 warp grid
    int g = lane >> 2, cq = lane & 3;       // groupID, threadID-in-group
    int m0 = blockIdx.y * 128, n0 = blockIdx.x * 128;

    // per-thread load coordinates (fixed across k): rows lr+32j, cols lc*4..lc*4+3
    int lr = tid >> 3, lc = tid & 7;
    const float* aptr[4];
    const float* bptr[4];
#pragma unroll
    for (int j = 0; j < 4; j++) {
        int m = m0 + lr + 32 * j;
        aptr[j] = tok ? A + (size_t)tok[m] * lda : A + (size_t)m * lda;
        int n = n0 + lr + 32 * j;
        bptr[j] = (n < N) ? Bm + (size_t)n * ldb : Bm;
    }

    int nk = K >> 5;   // k-chunks of 32

    // prologue: stage 0 and 1
#pragma unroll
    for (int s = 0; s < GSTAGES - 1; s++) {
#pragma unroll
        for (int j = 0; j < 4; j++) {
            cp16(&As[s][lr + 32 * j][lc * 4], aptr[j] + s * 32 + lc * 4);
            cp16(&Bs[s][lr + 32 * j][lc * 4], bptr[j] + s * 32 + lc * 4);
        }
        cp_commit();
    }

    float acc[4][4][4];
#pragma unroll
    for (int i = 0; i < 4; i++)
#pragma unroll
        for (int j = 0; j < 4; j++)
#pragma unroll
            for (int r = 0; r < 4; r++) acc[i][j][r] = 0.f;

    for (int kt = 0; kt < nk; kt++) {
        cp_wait1();            // chunk kt resident
        __syncthreads();       // ...for every thread; prior mma reads also done

        int kn = kt + GSTAGES - 1;
        if (kn < nk) {
            int s = kn % GSTAGES;
#pragma unroll
            for (int j = 0; j < 4; j++) {
                cp16(&As[s][lr + 32 * j][lc * 4], aptr[j] + kn * 32 + lc * 4);
                cp16(&Bs[s][lr + 32 * j][lc * 4], bptr[j] + kn * 32 + lc * 4);
            }
        }
        cp_commit();           // unconditional: keeps group accounting uniform

        int st = kt % GSTAGES;
#pragma unroll
        for (int kk = 0; kk < 32; kk += 8) {
            uint32_t af[4][4], bf[4][2];
#pragma unroll
            for (int tm = 0; tm < 4; tm++) {
                int rb = wm * 64 + tm * 16;
                af[tm][0] = As[st][rb + g][kk + cq];
                af[tm][1] = As[st][rb + g + 8][kk + cq];
                af[tm][2] = As[st][rb + g][kk + cq + 4];
                af[tm][3] = As[st][rb + g + 8][kk + cq + 4];
            }
#pragma unroll
            for (int tn = 0; tn < 4; tn++) {
                int cb = wn * 32 + tn * 8;
                bf[tn][0] = Bs[st][cb + g][kk + cq];
                bf[tn][1] = Bs[st][cb + g][kk + cq + 4];
            }
#pragma unroll
            for (int tm = 0; tm < 4; tm++)
#pragma unroll
                for (int tn = 0; tn < 4; tn++) {
                    asm volatile(
                        "mma.sync.aligned.m16n8k8.row.col.f32.tf32.tf32.f32 "
                        "{%0,%1,%2,%3}, {%4,%5,%6,%7}, {%8,%9}, {%0,%1,%2,%3};"
                        : "+f"(acc[tm][tn][0]), "+f"(acc[tm][tn][1]),
                          "+f"(acc[tm][tn][2]), "+f"(acc[tm][tn][3])
                        : "r"(af[tm][0]), "r"(af[tm][1]), "r"(af[tm][2]), "r"(af[tm][3]),
                          "r"(bf[tn][0]), "r"(bf[tn][1]));
                }
        }
        __syncthreads();       // all reads of stage st done before it is refilled
    }

    // epilogue: c0:(g,2cq) c1:(g,2cq+1) c2:(g+8,2cq) c3:(g+8,2cq+1)
#pragma unroll
    for (int tm = 0; tm < 4; tm++) {
        int rowA = m0 + wm * 64 + tm * 16 + g;
        int rowB = rowA + 8;
        const float* adA = addend ? addend + (size_t)rowA * ldadd : nullptr;
        const float* adB = addend ? addend + (size_t)rowB * ldadd : nullptr;
        float* cA = C + (size_t)rowA * ldc;
        float* cB = C + (size_t)rowB * ldc;
#pragma unroll
        for (int tn = 0; tn < 4; tn++) {
            int col = n0 + wn * 32 + tn * 8 + cq * 2;
            if (col < N) {   // N even at all call sites, so col+1 < N too
                float b0 = bias ? bias[col] : 0.f;
                float b1 = bias ? bias[col + 1] : 0.f;
                cA[col]     = acc[tm][tn][0] + b0 + (adA ? adA[col] : 0.f);
                cA[col + 1] = acc[tm][tn][1] + b1 + (adA ? adA[col + 1] : 0.f);
                cB[col]     = acc[tm][tn][2] + b0 + (adB ? adB[col] : 0.f);
                cB[col + 1] = acc[tm][tn][3] + b1 + (adB ? adB[col + 1] : 0.f);
            }
        }
    }
}

// ---------------- persistent encoder LSTM (all 64 steps, one launch) ----------------
__global__ void __launch_bounds__(256) enc_persist_k(
    const float* __restrict__ xw, const float* __restrict__ Whh,
    float* __restrict__ hbuf,
    float* __restrict__ fhid, float* __restrict__ bhid,
    unsigned* __restrict__ bar)
{
    __shared__ __align__(16) float4 wsm[4][H_];   // 32 KB
    __shared__ float hs[BB_][33];                 // 8.25 KB staging

    int tid = threadIdx.x, warp = tid >> 5, lane = tid & 31;
    int cl = warp >> 1;                  // local column 0..3
    int c = blockIdx.x * 4 + cl;         // global h column
    int row = ((warp & 1) << 5) + lane;  // batch row 0..63

    for (int i = tid; i < 4 * H_; i += 256) {
        int icl = i >> 9, k = i & (H_ - 1);
        int cc = blockIdx.x * 4 + icl;
        wsm[icl][k] = make_float4(
            Whh[(size_t)(0 * H_ + cc) * H_ + k],
            Whh[(size_t)(1 * H_ + cc) * H_ + k],
            Whh[(size_t)(2 * H_ + cc) * H_ + k],
            Whh[(size_t)(3 * H_ + cc) * H_ + k]);
    }

    float cstate = 0.f;
    unsigned nb = gridDim.x;

    for (int t = 0; t < T_; t++) {
        const float* hprev = hbuf + (size_t)(t % 3) * (BB_ * H_);
        float* hnext = hbuf + (size_t)((t + 1) % 3) * (BB_ * H_);

        float ai = 0.f, af = 0.f, ag = 0.f, ao = 0.f;
        for (int k0 = 0; k0 < H_; k0 += 32) {
            __syncthreads();
            for (int li = tid; li < BB_ * 8; li += 256) {
                int r = li >> 3, c4 = li & 7;
                float4 v = __ldcg(reinterpret_cast<const float4*>(hprev + (size_t)r * H_ + k0) + c4);
                hs[r][c4 * 4 + 0] = v.x; hs[r][c4 * 4 + 1] = v.y;
                hs[r][c4 * 4 + 2] = v.z; hs[r][c4 * 4 + 3] = v.w;
            }
            __syncthreads();
#pragma unroll
            for (int kk = 0; kk < 32; kk++) {
                float hv = hs[row][kk];
                float4 w = wsm[cl][k0 + kk];
                ai += w.x * hv; af += w.y * hv; ag += w.z * hv; ao += w.w * hv;
            }
        }

        const float* xrow = xw + ((size_t)t * BB_ + row) * G_;
        float gi = ai + xrow[c];
        float gf = af + xrow[H_ + c];
        float gg = ag + xrow[2 * H_ + c];
        float go = ao + xrow[3 * H_ + c];
        float I = sigf(gi), F = sigf(gf), Gv = tanhf(gg), O = sigf(go);
        cstate = F * cstate + I * Gv;
        float hn = O * tanhf(cstate);
        hnext[(size_t)row * H_ + c] = hn;
        if (row < B_) fhid[((size_t)t * B_ + row) * H_ + c] = hn;
        else          bhid[((size_t)t * B_ + (row - B_)) * H_ + c] = hn;

        if (t == T_ - 1) break;

        __threadfence();
        __syncthreads();
        if (tid == 0) {
            atomicAdd(bar, 1u);
            unsigned target = (unsigned)(t + 1) * nb;
            while (atomicAdd(bar, 0u) < target) __nanosleep(40);
        }
        __syncthreads();
    }
}

// ---------------- decoder pointwise gates ----------------
__global__ void dec_gates_k(float* __restrict__ h, float* __restrict__ c, const float* __restrict__ g) {
    int idx = blockIdx.x * blockDim.x + threadIdx.x;
    if (idx >= N_ * H_) return;
    int r = idx >> 9, col = idx & 511;
    const float* gr = g + (size_t)r * G_;
    float I = sigf(gr[col]);
    float F = sigf(gr[H_ + col]);
    float Gv = tanhf(gr[2 * H_ + col]);
    float O = sigf(gr[3 * H_ + col]);
    float cn = F * c[idx] + I * Gv;
    c[idx] = cn;
    h[idx] = O * tanhf(cn);
}

// ---------------- per-row ONLINE logsumexp over V (single pass) + bookkeeping ----------------
__global__ void __launch_bounds__(256) reduce_k(
    const float* __restrict__ logits, const int* __restrict__ sent,
    float* __restrict__ cum, float* __restrict__ res, int s, int isBwd)
{
    __shared__ float sm[256];
    __shared__ float ss[256];
    int r = blockIdx.x, tid = threadIdx.x;
    const float* row = logits + (size_t)r * V_;
    float m = NEGF, su = 0.f;
    for (int i = tid; i < V_; i += 256) {
        float v = row[i];
        if (v > m) { su = su * expf(m - v) + 1.0f; m = v; }
        else       { su += expf(v - m); }
    }
    sm[tid] = m; ss[tid] = su; __syncthreads();
    for (int o = 128; o > 0; o >>= 1) {
        if (tid < o) {
            float ma = sm[tid], mb = sm[tid + o];
            float sa = ss[tid], sb = ss[tid + o];
            float mm = fmaxf(ma, mb);
            sm[tid] = mm;
            ss[tid] = sa * expf(ma - mm) + sb * expf(mb - mm);
        }
        __syncthreads();
    }
    if (tid == 0) {
        float logZ = sm[0] + logf(ss[0]);
        int mrow = r / B_, b = r % B_;
        if (s < W_) {
            int pos = min(mrow + s, T_ - 1);
            int y = isBwd ? sent[b * T_ + (T_ - 1 - pos)] : sent[b * T_ + pos];
            float lpy = row[y] - logZ;
            if (s == 0) {
                cum[r] = lpy;
            } else {
                float tag = row[0] - logZ;
                res[(s - 1) * N_ + r] = cum[r] + tag;
                cum[r] += lpy;
            }
        } else {
            float tag = row[0] - logZ;
            res[(W_ - 1) * N_ + r] = cum[r] + tag;
        }
    }
}

// ---------------- add_bidirection + semi-Markov DP + mean ----------------
__global__ void final_k(const float* __restrict__ fres, const float* __restrict__ bres, float* __restrict__ out) {
    int b = threadIdx.x;
    float b0 = 0.f, b1 = NEGF, b2 = NEGF;
    for (int e = 0; e < T_; e++) {
        int br = (T_ - 1 - e) * B_ + b;
        float p0 = fres[0 * N_ + e * B_ + b] + bres[0 * N_ + br];
        float p1 = (e >= 1) ? fres[1 * N_ + (e - 1) * B_ + b] + bres[1 * N_ + br] : NEGF;
        float p2 = (e >= 2) ? fres[2 * N_ + (e - 2) * B_ + b] + bres[2 * N_ + br] : NEGF;
        float v0 = b0 + p0, v1 = b1 + p1, v2 = b2 + p2;
        float mx = fmaxf(v0, fmaxf(v1, v2));
        float tot = mx + logf(expf(v0 - mx) + expf(v1 - mx) + expf(v2 - mx));
        b2 = b1; b1 = b0; b0 = tot;
    }
    float sum = b0;
    for (int o = 16; o > 0; o >>= 1) sum += __shfl_xor_sync(0xffffffffu, sum, o);
    if (b == 0) out[0] = -sum / (float)B_;
}

// ---------------- host launcher ----------------
extern "C" void kernel_launch(void* const* d_in, const int* in_sizes, int n_in,
                              void* d_out, int out_size)
{
    const int*   sent = (const int*)d_in[0];
    const float* emb  = (const float*)d_in[1];
    const float* eWih = (const float*)d_in[2];
    const float* eWhh = (const float*)d_in[3];
    const float* eb   = (const float*)d_in[4];
    const float* dWih[2] = {(const float*)d_in[5],  (const float*)d_in[10]};
    const float* dWhh[2] = {(const float*)d_in[6],  (const float*)d_in[11]};
    const float* db[2]   = {(const float*)d_in[7],  (const float*)d_in[12]};
    const float* dhW[2]  = {(const float*)d_in[8],  (const float*)d_in[13]};
    const float* dhb[2]  = {(const float*)d_in[9],  (const float*)d_in[14]};

    float *enc_xw, *hbuf, *fhid, *bhid, *dxw, *dg, *dh, *dc, *lgt, *cum, *fres, *bres;
    int *etok, *dtok;
    unsigned *bar;
    cudaGetSymbolAddress((void**)&enc_xw, g_enc_xw);
    cudaGetSymbolAddress((void**)&hbuf, g_hbuf);
    cudaGetSymbolAddress((void**)&bar, g_bar);
    cudaGetSymbolAddress((void**)&fhid, g_fwd_hid);
    cudaGetSymbolAddress((void**)&bhid, g_bwd_hid);
    cudaGetSymbolAddress((void**)&dxw, g_dec_xw);
    cudaGetSymbolAddress((void**)&dg, g_dec_g);
    cudaGetSymbolAddress((void**)&dh, g_dec_h);
    cudaGetSymbolAddress((void**)&dc, g_dec_c);
    cudaGetSymbolAddress((void**)&lgt, g_logits);
    cudaGetSymbolAddress((void**)&cum, g_cum);
    cudaGetSymbolAddress((void**)&fres, g_fres);
    cudaGetSymbolAddress((void**)&bres, g_bres);
    cudaGetSymbolAddress((void**)&etok, g_enc_tok);
    cudaGetSymbolAddress((void**)&dtok, g_dec_tok);

    cudaFuncSetAttribute(gemm_tf32_k, cudaFuncAttributeMaxDynamicSharedMemorySize, GSMEM_BYTES);

    // Encoder (fwd+bwd combined, batch 64)
    fill_enc_tok_k<<<(T_ * BB_ + 255) / 256, 256>>>(sent, etok);
    enc_init_k<<<(BB_ * H_ + 255) / 256, 256>>>(hbuf, bar);
    {
        dim3 grid(G_ / 128, (T_ * BB_) / 128);
        gemm_tf32_k<<<grid, 256, GSMEM_BYTES>>>(emb, E_, etok, eWih, E_, eb, nullptr, 0,
                                                enc_xw, G_, T_ * BB_, G_, E_);
    }
    enc_persist_k<<<ENC_BLOCKS, 256>>>(enc_xw, eWhh, hbuf, fhid, bhid, bar);

    // Decoders (fwd then bwd)
    for (int d = 0; d < 2; d++) {
        float* hid = d ? bhid : fhid;
        float* res = d ? bres : fres;
        fill_dec_tok_k<<<((W_ + 1) * N_ + 255) / 256, 256>>>(sent, d, dtok);
        {
            dim3 grid(G_ / 128, ((W_ + 1) * N_) / 128);
            gemm_tf32_k<<<grid, 256, GSMEM_BYTES>>>(emb, E_, dtok, dWih[d], E_, db[d], nullptr, 0,
                                                    dxw, G_, (W_ + 1) * N_, G_, E_);
        }
        dec_init_k<<<(N_ * H_ + 255) / 256, 256>>>(dh, dc, hid);
        for (int s = 0; s <= W_; s++) {
            dim3 gridg(G_ / 128, N_ / 128);
            gemm_tf32_k<<<gridg, 256, GSMEM_BYTES>>>(dh, H_, nullptr, dWhh[d], H_, nullptr,
                                                     dxw + (size_t)s * N_ * G_, G_, dg, G_, N_, G_, H_);
            dec_gates_k<<<(N_ * H_ + 255) / 256, 256>>>(dh, dc, dg);
            dim3 gridl((V_ + 127) / 128, N_ / 128);
            gemm_tf32_k<<<gridl, 256, GSMEM_BYTES>>>(dh, H_, nullptr, dhW[d], H_, dhb[d], nullptr, 0,
                                                     lgt, V_, N_, V_, H_);
            reduce_k<<<N_, 256>>>(lgt, sent, cum, res, s, d);
        }
    }

    final_k<<<1, 32>>>(fres, bres, (float*)d_out);
}